// round 13
// baseline (speedup 1.0000x reference)
#include <cuda_runtime.h>
#include <cuda_fp16.h>
#include <stdint.h>

#define NROWS 100000
#define NHID  128
#define EMAX  3200000
#define EPSBN 1e-5f
#define WTOT  983040

// mma GEMM geometry (fp16x3 split, m16n8k16)
#define BMM 256
#define BNN 128
#define KP32 12                   // uint32 (half2) stride per row: 8 data + 4 pad -> 48B
#define A_LO_OFF   12288          // bytes: 256*48
#define B_HI_OFF   24576
#define B_LO_OFF   30720
#define STAGE_B    36864
#define SMEM_MMA   73728          // 2 stages (R10-proven schedule)

// ---------------- scratch (no allocations allowed -> device globals) --------
__device__ float  g_hw [NROWS * NHID];
__device__ float  g_att[(size_t)NROWS * 640];   // attention logits (GEMM out)
__device__ float  g_x15[(size_t)NROWS * 640];   // fallback x15
__device__ float  g_h1 [NROWS * NHID];
__device__ float  g_h2 [NROWS * 32];
// pre-split fp16 hi/lo operand copies (A sides of all GEMMs)
__device__ __half g_xhi [(size_t)NROWS * 512];
__device__ __half g_xlo [(size_t)NROWS * 512];
__device__ __half g_x15hi[(size_t)NROWS * 640];
__device__ __half g_x15lo[(size_t)NROWS * 640];
__device__ __half g_athi[(size_t)NROWS * 640];
__device__ __half g_atlo[(size_t)NROWS * 640];
// CSR build scratch
__device__ int    g_cnt [NROWS];
__device__ int    g_pos [NROWS];
__device__ int    g_rowstart[NROWS + 1];
__device__ int    g_csrc[EMAX];
__device__ float  g_cval[EMAX];
// split-fp16 transposed weights: [N, K] K-major, hi + lo parts
__device__ __half g_wthi[WTOT];
__device__ __half g_wtlo[WTOT];

// ---------------- generic-PTX helpers (sm_80-level; no tcgen05) -------------
__device__ __forceinline__ uint32_t smem_u32(const void* p) {
    uint32_t a;
    asm("{ .reg .u64 t; cvta.to.shared.u64 t, %1; cvt.u32.u64 %0, t; }"
        : "=r"(a) : "l"(p));
    return a;
}
__device__ __forceinline__ void cpasync16(uint32_t dst, const void* src) {
    asm volatile("cp.async.cg.shared.global [%0], [%1], 16;" :: "r"(dst), "l"(src));
}
__device__ __forceinline__ void cpasync16z(uint32_t dst, const void* src, bool ok) {
    int sz = ok ? 16 : 0;
    asm volatile("cp.async.cg.shared.global [%0], [%1], 16, %2;"
                 :: "r"(dst), "l"(src), "r"(sz));
}
#define CP_COMMIT() asm volatile("cp.async.commit_group;" ::: "memory")
#define CP_WAIT0()  asm volatile("cp.async.wait_group 0;" ::: "memory")

// fp16 mma, K=16, fp32 accumulate
__device__ __forceinline__ void mma16(float* c, const uint32_t* a,
                                      uint32_t b0, uint32_t b1) {
    asm volatile(
        "mma.sync.aligned.m16n8k16.row.col.f32.f16.f16.f32 "
        "{%0,%1,%2,%3}, {%4,%5,%6,%7}, {%8,%9}, {%0,%1,%2,%3};"
        : "+f"(c[0]), "+f"(c[1]), "+f"(c[2]), "+f"(c[3])
        : "r"(a[0]), "r"(a[1]), "r"(a[2]), "r"(a[3]), "r"(b0), "r"(b1));
}

// ---- weight prep: W[K,N] -> hiT/loT [N,K] (fp16 hi/lo split) ---------------
__global__ void wsplit_kernel(const float* __restrict__ W,
                              __half* __restrict__ hiT, __half* __restrict__ loT,
                              int K, int N) {
    int i = blockIdx.x * 256 + threadIdx.x;
    if (i >= K * N) return;
    int k = i / N, n = i - k * N;
    float a = W[i];
    __half h = __float2half_rn(a);
    hiT[(long)n * K + k] = h;
    loT[(long)n * K + k] = __float2half_rn(a - __half2float(h));
}

// ---- x pre-split: fp32 [N,512] -> fp16 hi/lo same layout -------------------
__global__ void xsplit_kernel(const float* __restrict__ X) {
    long i = (long)blockIdx.x * 256 + threadIdx.x;
    if (i >= (long)NROWS * 512) return;
    float a = X[i];
    __half h = __float2half_rn(a);
    g_xhi[i] = h;
    g_xlo[i] = __float2half_rn(a - __half2float(h));
}

// ================= fp16x3 mma.sync GEMM (pre-split A, R10 schedule) =========
// C[rowTile:+256, colBase:+128] = [A0|A1] @ W  via Ahi*Bhi + Ahi*Blo + Alo*Bhi
// mode: 0 plain, 1 +bias, 2 +bias,BN-fold,ReLU
__global__ __launch_bounds__(256, 1) void gemm_mma_kernel(
    const __half* __restrict__ Ahi0, const __half* __restrict__ Alo0,
    int K0, int lda0,
    const __half* __restrict__ Ahi1, const __half* __restrict__ Alo1, int lda1,
    const __half* __restrict__ BhiT, const __half* __restrict__ BloT, int Ktot,
    const float* __restrict__ bias,
    const float* __restrict__ bng, const float* __restrict__ bnb,
    const float* __restrict__ bnm, const float* __restrict__ bnv,
    float* __restrict__ C, int ldc, int nrows, int mode)
{
    extern __shared__ char smem[];
    const int t      = threadIdx.x;
    const int lane   = t & 31;
    const int wid    = t >> 5;
    const int warp_m = wid >> 1;
    const int warp_n = wid & 1;
    const int rowTile = blockIdx.x * BMM;
    const int colBase = blockIdx.y * BNN;
    const uint32_t sbase = smem_u32(smem);

    float acc[4][8][4];
#pragma unroll
    for (int i = 0; i < 4; i++)
#pragma unroll
        for (int j = 0; j < 8; j++)
#pragma unroll
            for (int e = 0; e < 4; e++) acc[i][j][e] = 0.f;

    const int nch = Ktot >> 4;

    // A tile: 256 rows x 16 halves, hi+lo -> 1024 x 16B cp.async
    auto cpA = [&](int s, int kb) {
        uint32_t base = sbase + s * STAGE_B;
#pragma unroll
        for (int i = 0; i < 4; i++) {
            int id  = t + i * 256;
            int row = id >> 2, rem = id & 3;
            int part = rem >> 1, q = rem & 1;
            int ar  = rowTile + row;
            bool ok = ar < nrows;
            int arc = ok ? ar : 0;
            int kg  = kb + q * 8;
            const __half* src;
            if (kg < K0)
                src = (part ? Alo0 : Ahi0) + (long)arc * lda0 + kg;
            else
                src = (part ? Alo1 : Ahi1) + (long)arc * lda1 + (kg - K0);
            uint32_t dst = base + (part ? A_LO_OFF : 0) + row * 48 + q * 16;
            cpasync16z(dst, src, ok);
        }
    };
    // B tile: 128 n-rows x 16 halves, hi+lo -> 512 x 16B cp.async
    auto cpB = [&](int s, int kb) {
        uint32_t dst0 = sbase + s * STAGE_B;
#pragma unroll
        for (int i = 0; i < 2; i++) {
            int id   = t + i * 256;
            int n    = id >> 2;
            int rem  = id & 3;
            int part = rem >> 1, q = rem & 1;
            const __half* src = (part ? BloT : BhiT)
                                + (long)(colBase + n) * Ktot + kb + q * 8;
            uint32_t dst = dst0 + (part ? B_LO_OFF : B_HI_OFF) + n * 48 + q * 16;
            cpasync16(dst, src);
        }
    };
    auto compute = [&](int s) {
        const uint32_t* sAh = (const uint32_t*)(smem + s * STAGE_B);
        const uint32_t* sAl = (const uint32_t*)(smem + s * STAGE_B + A_LO_OFF);
        const uint32_t* sBh = (const uint32_t*)(smem + s * STAGE_B + B_HI_OFF);
        const uint32_t* sBl = (const uint32_t*)(smem + s * STAGE_B + B_LO_OFF);
        const int mrow = warp_m * 64 + (lane >> 2);
        const int nrow = warp_n * 64 + (lane >> 2);
        const int kq   = lane & 3;
        uint32_t ah[4][4], al[4][4];
#pragma unroll
        for (int mf = 0; mf < 4; mf++) {
            int m0 = mrow + mf * 16;
            ah[mf][0] = sAh[m0 * KP32 + kq];      ah[mf][1] = sAh[(m0 + 8) * KP32 + kq];
            ah[mf][2] = sAh[m0 * KP32 + kq + 4];  ah[mf][3] = sAh[(m0 + 8) * KP32 + kq + 4];
            al[mf][0] = sAl[m0 * KP32 + kq];      al[mf][1] = sAl[(m0 + 8) * KP32 + kq];
            al[mf][2] = sAl[m0 * KP32 + kq + 4];  al[mf][3] = sAl[(m0 + 8) * KP32 + kq + 4];
        }
#pragma unroll
        for (int nf = 0; nf < 8; nf++) {
            int n0 = nrow + nf * 8;
            uint32_t bh0 = sBh[n0 * KP32 + kq], bh1 = sBh[n0 * KP32 + kq + 4];
            uint32_t bl0 = sBl[n0 * KP32 + kq], bl1 = sBl[n0 * KP32 + kq + 4];
#pragma unroll
            for (int mf = 0; mf < 4; mf++) {
                mma16(acc[mf][nf], ah[mf], bh0, bh1);
                mma16(acc[mf][nf], ah[mf], bl0, bl1);
                mma16(acc[mf][nf], al[mf], bh0, bh1);
            }
        }
    };

    // ---- prologue (R10 style): stage 0 resident before loop ----
    cpA(0, 0); cpB(0, 0); CP_COMMIT();
    CP_WAIT0();
    __syncthreads();

    // ---- mainloop (R10-proven 2-stage: prefetch BEFORE compute) ----
    for (int ch = 0; ch < nch; ch++) {
        const int s = ch & 1;
        const bool more = (ch + 1 < nch);
        if (more) { cpA(s ^ 1, (ch + 1) << 4); cpB(s ^ 1, (ch + 1) << 4); CP_COMMIT(); }
        compute(s);
        if (more) CP_WAIT0();
        __syncthreads();
    }

    // ---- epilogue ----
#pragma unroll
    for (int mf = 0; mf < 4; mf++) {
        int r0 = rowTile + warp_m * 64 + mf * 16 + (lane >> 2);
#pragma unroll
        for (int nf = 0; nf < 8; nf++) {
            int cc = colBase + warp_n * 64 + nf * 8 + (lane & 3) * 2;
            float v0 = acc[mf][nf][0], v1 = acc[mf][nf][1];
            float v2 = acc[mf][nf][2], v3 = acc[mf][nf][3];
            if (mode == 1) {
                float b0 = bias[cc], b1 = bias[cc + 1];
                v0 += b0; v1 += b1; v2 += b0; v3 += b1;
            } else if (mode == 2) {
                float s0 = bng[cc]     * rsqrtf(bnv[cc]     + EPSBN);
                float s1 = bng[cc + 1] * rsqrtf(bnv[cc + 1] + EPSBN);
                float h0 = bnb[cc]     - bnm[cc]     * s0 + bias[cc]     * s0;
                float h1 = bnb[cc + 1] - bnm[cc + 1] * s1 + bias[cc + 1] * s1;
                v0 = fmaxf(0.f, v0 * s0 + h0); v1 = fmaxf(0.f, v1 * s1 + h1);
                v2 = fmaxf(0.f, v2 * s0 + h0); v3 = fmaxf(0.f, v3 * s1 + h1);
            }
            if (r0 < nrows)
                *(float2*)(C + (long)r0 * ldc + cc) = make_float2(v0, v1);
            if (r0 + 8 < nrows)
                *(float2*)(C + (long)(r0 + 8) * ldc + cc) = make_float2(v2, v3);
        }
    }
}

// ================= CSR build (once per launch; deterministic work) ==========
__global__ void csr_zero_kernel() {
    int i = blockIdx.x * blockDim.x + threadIdx.x;
    if (i < NROWS) { g_cnt[i] = 0; g_pos[i] = 0; }
}
__global__ void csr_hist_kernel(const int* __restrict__ dst, int E) {
    int e = blockIdx.x * blockDim.x + threadIdx.x;
    if (e < E) atomicAdd(&g_cnt[dst[e]], 1);
}
__global__ __launch_bounds__(1024) void csr_scan_kernel() {
    __shared__ int wsum[32];
    __shared__ int carry_s;
    const int t = threadIdx.x, lane = t & 31, w = t >> 5;
    if (t == 0) carry_s = 0;
    __syncthreads();
    for (int base = 0; base < NROWS; base += 1024) {
        int xv = (base + t < NROWS) ? g_cnt[base + t] : 0;
        int val = xv;
#pragma unroll
        for (int o = 1; o < 32; o <<= 1) {
            int y = __shfl_up_sync(0xffffffffu, val, o);
            if (lane >= o) val += y;
        }
        if (lane == 31) wsum[w] = val;
        __syncthreads();
        if (w == 0) {
            int s = wsum[lane];
#pragma unroll
            for (int o = 1; o < 32; o <<= 1) {
                int y = __shfl_up_sync(0xffffffffu, s, o);
                if (lane >= o) s += y;
            }
            wsum[lane] = s;
        }
        __syncthreads();
        int incl = val + (w ? wsum[w - 1] : 0) + carry_s;
        if (base + t < NROWS) g_rowstart[base + t] = incl - xv;
        __syncthreads();
        if (t == 1023) carry_s = incl;
        __syncthreads();
    }
    if (threadIdx.x == 0) g_rowstart[NROWS] = carry_s;
}
__global__ void csr_scatter_kernel(const int* __restrict__ src,
                                   const int* __restrict__ dst,
                                   const float* __restrict__ vals, int E) {
    int e = blockIdx.x * blockDim.x + threadIdx.x;
    if (e < E) {
        int d = dst[e];
        int p = g_rowstart[d] + atomicAdd(&g_pos[d], 1);
        g_csrc[p] = src[e];
        g_cval[p] = vals[e];
    }
}

// ---- SpMM segment-sum: warp per dst row; also emits fp16 hi/lo of x15 ------
__global__ __launch_bounds__(256) void spmm_csr_kernel(
    const float* __restrict__ bias,
    float* __restrict__ out,   // x15 + col-block base, ld 640
    int colOff, int do_relu)
{
    const int warp = (blockIdx.x * blockDim.x + threadIdx.x) >> 5;
    if (warp >= NROWS) return;
    const int lane = threadIdx.x & 31;
    const int s0 = g_rowstart[warp];
    const int s1 = g_rowstart[warp + 1];

    float ax = 0.f, ay = 0.f, az = 0.f, aw = 0.f;
    for (int base = s0; base < s1; base += 32) {
        int n = min(32, s1 - base);
        int   ss = 0; float vv = 0.f;
        if (lane < n) { ss = g_csrc[base + lane]; vv = g_cval[base + lane]; }
        for (int j = 0; j < n; j++) {
            int   s = __shfl_sync(0xffffffffu, ss, j);
            float v = __shfl_sync(0xffffffffu, vv, j);
            float4 h = *(const float4*)(g_hw + (long)s * 128 + lane * 4);
            ax = fmaf(v, h.x, ax); ay = fmaf(v, h.y, ay);
            az = fmaf(v, h.z, az); aw = fmaf(v, h.w, aw);
        }
    }
    float4 b = *(const float4*)(bias + lane * 4);
    ax += b.x; ay += b.y; az += b.z; aw += b.w;
    if (do_relu) {
        ax = fmaxf(0.f, ax); ay = fmaxf(0.f, ay);
        az = fmaxf(0.f, az); aw = fmaxf(0.f, aw);
    }
    *(float4*)(out + (long)warp * 640 + lane * 4) = make_float4(ax, ay, az, aw);
    // fp16 hi/lo copies for the GEMM A path (same rn split as before)
    __half hx = __float2half_rn(ax), hy = __float2half_rn(ay);
    __half hz = __float2half_rn(az), hw2 = __float2half_rn(aw);
    long hoff = (long)warp * 640 + colOff + lane * 4;
    *(__half2*)(g_x15hi + hoff)     = __halves2half2(hx, hy);
    *(__half2*)(g_x15hi + hoff + 2) = __halves2half2(hz, hw2);
    *(__half2*)(g_x15lo + hoff)     = __halves2half2(
        __float2half_rn(ax - __half2float(hx)), __float2half_rn(ay - __half2float(hy)));
    *(__half2*)(g_x15lo + hoff + 2) = __halves2half2(
        __float2half_rn(az - __half2float(hz)), __float2half_rn(aw - __half2float(hw2)));
}

// ---------------- attention softmax + mul; emits fp16 hi/lo of a ------------
__global__ void attn_kernel(const float* __restrict__ x15, int nrows) {
    int row = blockIdx.x * 8 + threadIdx.y;
    if (row >= nrows) return;
    int lane = threadIdx.x;
    const float* ar = g_att + (long)row * 640;
    float z[20];
    float mx = -1e30f;
#pragma unroll
    for (int i = 0; i < 20; i++) { z[i] = ar[lane + 32 * i]; mx = fmaxf(mx, z[i]); }
#pragma unroll
    for (int o = 16; o; o >>= 1) mx = fmaxf(mx, __shfl_xor_sync(0xffffffffu, mx, o));
    float s = 0.f;
#pragma unroll
    for (int i = 0; i < 20; i++) { z[i] = expf(z[i] - mx); s += z[i]; }
#pragma unroll
    for (int o = 16; o; o >>= 1) s += __shfl_xor_sync(0xffffffffu, s, o);
    float inv = 1.0f / s;
    const float* xr = x15 + (long)row * 640;
    __half* dh = g_athi + (long)row * 640;
    __half* dl = g_atlo + (long)row * 640;
#pragma unroll
    for (int i = 0; i < 20; i++) {
        int c = lane + 32 * i;
        float av = xr[c] * z[i] * inv;
        __half h = __float2half_rn(av);
        dh[c] = h;
        dl[c] = __float2half_rn(av - __half2float(h));
    }
}

// ---------------- H2: relu(bn2(h1 @ W2 + b2)), [N,128]x[128,32] -------------
__global__ void h2_kernel(const float* __restrict__ W, const float* __restrict__ bias,
                          const float* __restrict__ g, const float* __restrict__ b,
                          const float* __restrict__ m, const float* __restrict__ v,
                          int nrows)
{
    __shared__ float Ws[128 * 32];
    int t = threadIdx.x;
    for (int i = t; i < 4096; i += 256) Ws[i] = W[i];
    __syncthreads();
    int col = t & 31;
    int r = blockIdx.x * 8 + (t >> 5);
    if (r >= nrows) return;
    const float* hr = g_h1 + (long)r * 128;
    float s = 0.f;
#pragma unroll
    for (int k = 0; k < 128; k++) s += __ldg(hr + k) * Ws[k * 32 + col];
    float scv = g[col] * rsqrtf(v[col] + EPSBN);
    float shv = b[col] - m[col] * scv;
    g_h2[(long)r * 32 + col] = fmaxf(0.f, (s + bias[col]) * scv + shv);
}

// ---------------- H3 + log_softmax (thread per row) --------------------------
__global__ void h3_kernel(const float* __restrict__ W, const float* __restrict__ bias,
                          float* __restrict__ out, int nrows)
{
    __shared__ float Ws[320];
    __shared__ float bs[10];
    int t = threadIdx.x;
    for (int i = t; i < 320; i += 256) Ws[i] = W[i];
    if (t < 10) bs[t] = bias[t];
    __syncthreads();
    int r = blockIdx.x * 256 + t;
    if (r >= nrows) return;
    float h[32];
    const float4* hr = (const float4*)(g_h2 + (long)r * 32);
#pragma unroll
    for (int i = 0; i < 8; i++) {
        float4 x = hr[i];
        h[4*i] = x.x; h[4*i+1] = x.y; h[4*i+2] = x.z; h[4*i+3] = x.w;
    }
    float lg[10];
#pragma unroll
    for (int c = 0; c < 10; c++) {
        float s = bs[c];
#pragma unroll
        for (int k = 0; k < 32; k++) s += h[k] * Ws[k * 10 + c];
        lg[c] = s;
    }
    float mx = lg[0];
#pragma unroll
    for (int c = 1; c < 10; c++) mx = fmaxf(mx, lg[c]);
    float se = 0.f;
#pragma unroll
    for (int c = 0; c < 10; c++) se += expf(lg[c] - mx);
    float lse = mx + logf(se);
#pragma unroll
    for (int c = 0; c < 10; c++) out[(long)r * 10 + c] = lg[c] - lse;
}

// ---------------- host orchestration ----------------------------------------
extern "C" void kernel_launch(void* const* d_in, const int* in_sizes, int n_in,
                              void* d_out, int out_size)
{
    const float* x     = (const float*)d_in[0];
    const int*   esrc  = (const int*)  d_in[1];
    const int*   edst  = (const int*)  d_in[2];
    const float* evals = (const float*)d_in[3];
    const float* Wg[5] = {(const float*)d_in[4],  (const float*)d_in[6],
                          (const float*)d_in[8],  (const float*)d_in[10],
                          (const float*)d_in[12]};
    const float* bg[5] = {(const float*)d_in[5],  (const float*)d_in[7],
                          (const float*)d_in[9],  (const float*)d_in[11],
                          (const float*)d_in[13]};
    const float* Wa  = (const float*)d_in[14]; const float* ba  = (const float*)d_in[15];
    const float* H1w = (const float*)d_in[16]; const float* H1b = (const float*)d_in[17];
    const float* bn1g = (const float*)d_in[18]; const float* bn1b = (const float*)d_in[19];
    const float* bn1m = (const float*)d_in[20]; const float* bn1v = (const float*)d_in[21];
    const float* H2w = (const float*)d_in[22]; const float* H2b = (const float*)d_in[23];
    const float* bn2g = (const float*)d_in[24]; const float* bn2b = (const float*)d_in[25];
    const float* bn2m = (const float*)d_in[26]; const float* bn2v = (const float*)d_in[27];
    const float* H3w = (const float*)d_in[28]; const float* H3b = (const float*)d_in[29];
    const int E = in_sizes[1];
    (void)n_in;

    float *hw, *att, *x15f, *h1;
    __half *wthi, *wtlo, *xhi, *xlo, *x15hi, *x15lo, *athi, *atlo;
    cudaGetSymbolAddress((void**)&hw,    g_hw);
    cudaGetSymbolAddress((void**)&att,   g_att);
    cudaGetSymbolAddress((void**)&x15f,  g_x15);
    cudaGetSymbolAddress((void**)&h1,    g_h1);
    cudaGetSymbolAddress((void**)&wthi,  g_wthi);
    cudaGetSymbolAddress((void**)&wtlo,  g_wtlo);
    cudaGetSymbolAddress((void**)&xhi,   g_xhi);
    cudaGetSymbolAddress((void**)&xlo,   g_xlo);
    cudaGetSymbolAddress((void**)&x15hi, g_x15hi);
    cudaGetSymbolAddress((void**)&x15lo, g_x15lo);
    cudaGetSymbolAddress((void**)&athi,  g_athi);
    cudaGetSymbolAddress((void**)&atlo,  g_atlo);

    cudaFuncSetAttribute(gemm_mma_kernel,
                         cudaFuncAttributeMaxDynamicSharedMemorySize, SMEM_MMA);

    float* out = (float*)d_out;
    float* x15;
    float* logits = nullptr;
    if (out_size >= NROWS * 650)      { logits = out; x15 = out + (long)NROWS * 10; }
    else if (out_size == NROWS * 640) { x15 = out; }
    else                              { logits = out; x15 = x15f; }

    const int EB = (E + 255) / 256;
    const int RB = (NROWS * 32 + 255) / 256;
    const int GM = (NROWS + BMM - 1) / BMM;

    // ---- weight transpose + fp16 split; x pre-split (once per launch) ----
    const long woff[7] = {0, 65536, 147456, 245760, 360448, 491520, 901120};
    const int  wk  [7] = {512, 640, 768, 896, 1024, 640, 640};
    const int  wn  [7] = {128, 128, 128, 128, 128, 640, 128};
    const float* wsrc[7] = {Wg[0], Wg[1], Wg[2], Wg[3], Wg[4], Wa, H1w};
    for (int i = 0; i < 7; i++) {
        int total = wk[i] * wn[i];
        wsplit_kernel<<<(total + 255) / 256, 256>>>(wsrc[i],
                                                    wthi + woff[i], wtlo + woff[i],
                                                    wk[i], wn[i]);
    }
    xsplit_kernel<<<(int)(((long)NROWS * 512 + 255) / 256), 256>>>(x);

    // ---- CSR build (once; reused by all 5 layers) ----
    csr_zero_kernel<<<(NROWS + 255) / 256, 256>>>();
    csr_hist_kernel<<<EB, 256>>>(edst, E);
    csr_scan_kernel<<<1, 1024>>>();
    csr_scatter_kernel<<<EB, 256>>>(esrc, edst, evals, E);

    // ---- 5 dense-GCN layers (concat folded into two-part pre-split A) ----
    for (int L = 0; L < 5; L++) {
        int Ktot = 512 + L * 128;
        gemm_mma_kernel<<<dim3(GM, 1), 256, SMEM_MMA>>>(
            xhi, xlo, 512, 512,
            x15hi, x15lo, 640,
            wthi + woff[L], wtlo + woff[L], Ktot,
            nullptr, nullptr, nullptr, nullptr, nullptr,
            hw, 128, NROWS, 0);
        spmm_csr_kernel<<<RB, 256>>>(bg[L], x15 + L * 128, L * 128, (L == 0) ? 1 : 0);
    }

    if (logits) {
        // ---- attention: att = x15 @ Wa + ba ; a = x15 * softmax(att) ----
        gemm_mma_kernel<<<dim3(GM, 5), 256, SMEM_MMA>>>(
            x15hi, x15lo, 640, 640,
            x15hi, x15lo, 640,
            wthi + woff[5], wtlo + woff[5], 640,
            ba, nullptr, nullptr, nullptr, nullptr,
            att, 640, NROWS, 1);
        attn_kernel<<<(NROWS + 7) / 8, dim3(32, 8)>>>(x15, NROWS);
        // ---- head: h1 = relu(bn1(a @ H1w + H1b)) ----
        gemm_mma_kernel<<<dim3(GM, 1), 256, SMEM_MMA>>>(
            athi, atlo, 640, 640,
            athi, atlo, 640,
            wthi + woff[6], wtlo + woff[6], 640,
            H1b, bn1g, bn1b, bn1m, bn1v,
            h1, 128, NROWS, 2);
        h2_kernel<<<(NROWS + 7) / 8, 256>>>(H2w, H2b, bn2g, bn2b, bn2m, bn2v, NROWS);
        h3_kernel<<<(NROWS + 255) / 256, 256>>>(H3w, H3b, logits, NROWS);
    }
}

// round 15
// speedup vs baseline: 1.1211x; 1.1211x over previous
#include <cuda_runtime.h>
#include <cuda_fp16.h>
#include <stdint.h>

#define NROWS 100000
#define NHID  128
#define EMAX  3200000
#define EPSBN 1e-5f
#define WTOT  983040

// mma GEMM geometry (fp16x3 split, m16n8k16) — exact R10 configuration
#define BMM 256
#define BNN 128
#define KP32 12                   // uint32 (half2) stride per row: 8 data + 4 pad -> 48B
#define A_LO_OFF   12288          // bytes: 256*48
#define B_HI_OFF   24576
#define B_LO_OFF   30720
#define STAGE_B    36864
#define SMEM_MMA   73728          // 2 stages

// ---------------- scratch (no allocations allowed -> device globals) --------
__device__ float  g_hw [NROWS * NHID];
__device__ float  g_att[(size_t)NROWS * 640];
__device__ float  g_x15[(size_t)NROWS * 640];
__device__ float  g_h1 [NROWS * NHID];
// CSR build scratch
__device__ int    g_cnt [NROWS];
__device__ int    g_pos [NROWS];
__device__ int    g_rowstart[NROWS + 1];
__device__ int    g_csrc[EMAX];
__device__ float  g_cval[EMAX];
// split-fp16 transposed weights: [N, K] K-major, hi + lo parts
__device__ __half g_wthi[WTOT];
__device__ __half g_wtlo[WTOT];

// ---------------- generic-PTX helpers (sm_80-level; no tcgen05) -------------
__device__ __forceinline__ uint32_t smem_u32(const void* p) {
    uint32_t a;
    asm("{ .reg .u64 t; cvta.to.shared.u64 t, %1; cvt.u32.u64 %0, t; }"
        : "=r"(a) : "l"(p));
    return a;
}
__device__ __forceinline__ void cpasync16(uint32_t dst, const void* src) {
    asm volatile("cp.async.cg.shared.global [%0], [%1], 16;" :: "r"(dst), "l"(src));
}
#define CP_COMMIT() asm volatile("cp.async.commit_group;" ::: "memory")
#define CP_WAIT0()  asm volatile("cp.async.wait_group 0;" ::: "memory")

// fp16 mma, K=16, fp32 accumulate
__device__ __forceinline__ void mma16(float* c, const uint32_t* a,
                                      uint32_t b0, uint32_t b1) {
    asm volatile(
        "mma.sync.aligned.m16n8k16.row.col.f32.f16.f16.f32 "
        "{%0,%1,%2,%3}, {%4,%5,%6,%7}, {%8,%9}, {%0,%1,%2,%3};"
        : "+f"(c[0]), "+f"(c[1]), "+f"(c[2]), "+f"(c[3])
        : "r"(a[0]), "r"(a[1]), "r"(a[2]), "r"(a[3]), "r"(b0), "r"(b1));
}
__device__ __forceinline__ uint32_t pack_hi(float x, float y, uint32_t& lo) {
    __half hx = __float2half_rn(x);
    __half hy = __float2half_rn(y);
    __half lx = __float2half_rn(x - __half2float(hx));
    __half ly = __float2half_rn(y - __half2float(hy));
    __half2 l2 = __halves2half2(lx, ly);
    lo = *(uint32_t*)&l2;
    __half2 h2 = __halves2half2(hx, hy);
    return *(uint32_t*)&h2;
}

// ---- weight prep: W[K,N] -> hiT/loT [N,K] (fp16 hi/lo split) ---------------
__global__ void wsplit_kernel(const float* __restrict__ W,
                              __half* __restrict__ hiT, __half* __restrict__ loT,
                              int K, int N) {
    int i = blockIdx.x * 256 + threadIdx.x;
    if (i >= K * N) return;
    int k = i / N, n = i - k * N;
    float a = W[i];
    __half h = __float2half_rn(a);
    hiT[(long)n * K + k] = h;
    loT[(long)n * K + k] = __float2half_rn(a - __half2float(h));
}

// ================= fp16x3 mma.sync GEMM (exact R10) =========================
// C[rowTile:+256, colBase:+128] = [A0|A1] @ W  via Ahi*Bhi + Ahi*Blo + Alo*Bhi
// mode: 0 plain, 1 +bias, 2 +bias,BN-fold,ReLU
__global__ __launch_bounds__(256, 1) void gemm_mma_kernel(
    const float* __restrict__ A0, int K0, int lda0,
    const float* __restrict__ A1, int lda1,
    const __half* __restrict__ BhiT, const __half* __restrict__ BloT, int Ktot,
    const float* __restrict__ bias,
    const float* __restrict__ bng, const float* __restrict__ bnb,
    const float* __restrict__ bnm, const float* __restrict__ bnv,
    float* __restrict__ C, int ldc, int nrows, int mode)
{
    extern __shared__ char smem[];
    const int t      = threadIdx.x;
    const int lane   = t & 31;
    const int wid    = t >> 5;
    const int warp_m = wid >> 1;
    const int warp_n = wid & 1;
    const int rowTile = blockIdx.x * BMM;
    const int colBase = blockIdx.y * BNN;
    const uint32_t sbase = smem_u32(smem);

    float acc[4][8][4];
#pragma unroll
    for (int i = 0; i < 4; i++)
#pragma unroll
        for (int j = 0; j < 8; j++)
#pragma unroll
            for (int e = 0; e < 4; e++) acc[i][j][e] = 0.f;

    const int nch = Ktot >> 4;
    float4 areg[4];

    auto ldA = [&](int kb) {
#pragma unroll
        for (int i = 0; i < 4; i++) {
            int id  = t + i * 256;
            int row = id >> 2, q = id & 3;
            int ar  = rowTile + row;
            float4 v = make_float4(0.f, 0.f, 0.f, 0.f);
            if (ar < nrows) {
                int kg = kb + q * 4;   // chunk never straddles K0 (both mult of 16)
                const float* ap = (kg < K0) ? A0 + (long)ar * lda0 + kg
                                            : A1 + (long)ar * lda1 + (kg - K0);
                v = *(const float4*)ap;
            }
            areg[i] = v;
        }
    };
    // split + STS A regs into stage s (half2 hi/lo)
    auto stA = [&](int s) {
        char* base = smem + s * STAGE_B;
#pragma unroll
        for (int i = 0; i < 4; i++) {
            int id  = t + i * 256;
            int row = id >> 2, q = id & 3;
            float4 v = areg[i];
            uint32_t lo0, lo1;
            uint32_t hi0 = pack_hi(v.x, v.y, lo0);
            uint32_t hi1 = pack_hi(v.z, v.w, lo1);
            int off = row * 48 + q * 8;            // bytes
            *(uint2*)(base + off)            = make_uint2(hi0, hi1);
            *(uint2*)(base + A_LO_OFF + off) = make_uint2(lo0, lo1);
        }
    };
    // B cp.async into stage s: 128 n-rows x 16 halves (32B = 2x16B), hi+lo
    auto cpB = [&](int s, int kb) {
        uint32_t dst0 = sbase + s * STAGE_B;
#pragma unroll
        for (int i = 0; i < 2; i++) {
            int id   = t + i * 256;
            int n    = id >> 2;
            int rem  = id & 3;
            int part = rem >> 1, q = rem & 1;
            const __half* src = (part ? BloT : BhiT)
                                + (long)(colBase + n) * Ktot + kb + q * 8;
            uint32_t dst = dst0 + (part ? B_LO_OFF : B_HI_OFF) + n * 48 + q * 16;
            cpasync16(dst, src);
        }
    };
    auto compute = [&](int s) {
        const uint32_t* sAh = (const uint32_t*)(smem + s * STAGE_B);
        const uint32_t* sAl = (const uint32_t*)(smem + s * STAGE_B + A_LO_OFF);
        const uint32_t* sBh = (const uint32_t*)(smem + s * STAGE_B + B_HI_OFF);
        const uint32_t* sBl = (const uint32_t*)(smem + s * STAGE_B + B_LO_OFF);
        const int mrow = warp_m * 64 + (lane >> 2);
        const int nrow = warp_n * 64 + (lane >> 2);
        const int kq   = lane & 3;
        uint32_t ah[4][4], al[4][4];
#pragma unroll
        for (int mf = 0; mf < 4; mf++) {
            int m0 = mrow + mf * 16;
            ah[mf][0] = sAh[m0 * KP32 + kq];      ah[mf][1] = sAh[(m0 + 8) * KP32 + kq];
            ah[mf][2] = sAh[m0 * KP32 + kq + 4];  ah[mf][3] = sAh[(m0 + 8) * KP32 + kq + 4];
            al[mf][0] = sAl[m0 * KP32 + kq];      al[mf][1] = sAl[(m0 + 8) * KP32 + kq];
            al[mf][2] = sAl[m0 * KP32 + kq + 4];  al[mf][3] = sAl[(m0 + 8) * KP32 + kq + 4];
        }
#pragma unroll
        for (int nf = 0; nf < 8; nf++) {
            int n0 = nrow + nf * 8;
            uint32_t bh0 = sBh[n0 * KP32 + kq], bh1 = sBh[n0 * KP32 + kq + 4];
            uint32_t bl0 = sBl[n0 * KP32 + kq], bl1 = sBl[n0 * KP32 + kq + 4];
#pragma unroll
            for (int mf = 0; mf < 4; mf++) {
                mma16(acc[mf][nf], ah[mf], bh0, bh1);
                mma16(acc[mf][nf], ah[mf], bl0, bl1);
                mma16(acc[mf][nf], al[mf], bh0, bh1);
            }
        }
    };

    // ---- prologue ----
    ldA(0);
    cpB(0, 0);
    CP_COMMIT();
    stA(0);
    CP_WAIT0();
    __syncthreads();

    // ---- mainloop (R10-proven 2-stage) ----
    for (int ch = 0; ch < nch; ch++) {
        const int s = ch & 1;
        const bool more = (ch + 1 < nch);
        if (more) { ldA((ch + 1) << 4); cpB(s ^ 1, (ch + 1) << 4); CP_COMMIT(); }
        compute(s);
        if (more) { stA(s ^ 1); CP_WAIT0(); }
        __syncthreads();
    }

    // ---- epilogue ----
#pragma unroll
    for (int mf = 0; mf < 4; mf++) {
        int r0 = rowTile + warp_m * 64 + mf * 16 + (lane >> 2);
#pragma unroll
        for (int nf = 0; nf < 8; nf++) {
            int cc = colBase + warp_n * 64 + nf * 8 + (lane & 3) * 2;
            float v0 = acc[mf][nf][0], v1 = acc[mf][nf][1];
            float v2 = acc[mf][nf][2], v3 = acc[mf][nf][3];
            if (mode == 1) {
                float b0 = bias[cc], b1 = bias[cc + 1];
                v0 += b0; v1 += b1; v2 += b0; v3 += b1;
            } else if (mode == 2) {
                float s0 = bng[cc]     * rsqrtf(bnv[cc]     + EPSBN);
                float s1 = bng[cc + 1] * rsqrtf(bnv[cc + 1] + EPSBN);
                float h0 = bnb[cc]     - bnm[cc]     * s0 + bias[cc]     * s0;
                float h1 = bnb[cc + 1] - bnm[cc + 1] * s1 + bias[cc + 1] * s1;
                v0 = fmaxf(0.f, v0 * s0 + h0); v1 = fmaxf(0.f, v1 * s1 + h1);
                v2 = fmaxf(0.f, v2 * s0 + h0); v3 = fmaxf(0.f, v3 * s1 + h1);
            }
            if (r0 < nrows)
                *(float2*)(C + (long)r0 * ldc + cc) = make_float2(v0, v1);
            if (r0 + 8 < nrows)
                *(float2*)(C + (long)(r0 + 8) * ldc + cc) = make_float2(v2, v3);
        }
    }
}

// ================= CSR build (once per launch; deterministic work) ==========
__global__ void csr_zero_kernel() {
    int i = blockIdx.x * blockDim.x + threadIdx.x;
    if (i < NROWS) { g_cnt[i] = 0; g_pos[i] = 0; }
}
__global__ void csr_hist_kernel(const int* __restrict__ dst, int E) {
    int e = blockIdx.x * blockDim.x + threadIdx.x;
    if (e < E) atomicAdd(&g_cnt[dst[e]], 1);
}
__global__ __launch_bounds__(1024) void csr_scan_kernel() {
    __shared__ int wsum[32];
    __shared__ int carry_s;
    const int t = threadIdx.x, lane = t & 31, w = t >> 5;
    if (t == 0) carry_s = 0;
    __syncthreads();
    for (int base = 0; base < NROWS; base += 1024) {
        int xv = (base + t < NROWS) ? g_cnt[base + t] : 0;
        int val = xv;
#pragma unroll
        for (int o = 1; o < 32; o <<= 1) {
            int y = __shfl_up_sync(0xffffffffu, val, o);
            if (lane >= o) val += y;
        }
        if (lane == 31) wsum[w] = val;
        __syncthreads();
        if (w == 0) {
            int s = wsum[lane];
#pragma unroll
            for (int o = 1; o < 32; o <<= 1) {
                int y = __shfl_up_sync(0xffffffffu, s, o);
                if (lane >= o) s += y;
            }
            wsum[lane] = s;
        }
        __syncthreads();
        int incl = val + (w ? wsum[w - 1] : 0) + carry_s;
        if (base + t < NROWS) g_rowstart[base + t] = incl - xv;
        __syncthreads();
        if (t == 1023) carry_s = incl;
        __syncthreads();
    }
    if (threadIdx.x == 0) g_rowstart[NROWS] = carry_s;
}
__global__ void csr_scatter_kernel(const int* __restrict__ src,
                                   const int* __restrict__ dst,
                                   const float* __restrict__ vals, int E) {
    int e = blockIdx.x * blockDim.x + threadIdx.x;
    if (e < E) {
        int d = dst[e];
        int p = g_rowstart[d] + atomicAdd(&g_pos[d], 1);
        g_csrc[p] = src[e];
        g_cval[p] = vals[e];
    }
}

// ---- SpMM segment-sum: warp per dst row, no atomics (exact R10) ------------
__global__ __launch_bounds__(256) void spmm_csr_kernel(
    const float* __restrict__ bias,
    float* __restrict__ out,   // x15 + col-block base, ld 640
    int do_relu)
{
    const int warp = (blockIdx.x * blockDim.x + threadIdx.x) >> 5;
    if (warp >= NROWS) return;
    const int lane = threadIdx.x & 31;
    const int s0 = g_rowstart[warp];
    const int s1 = g_rowstart[warp + 1];

    float ax = 0.f, ay = 0.f, az = 0.f, aw = 0.f;
    for (int base = s0; base < s1; base += 32) {
        int n = min(32, s1 - base);
        int   ss = 0; float vv = 0.f;
        if (lane < n) { ss = g_csrc[base + lane]; vv = g_cval[base + lane]; }
        for (int j = 0; j < n; j++) {
            int   s = __shfl_sync(0xffffffffu, ss, j);
            float v = __shfl_sync(0xffffffffu, vv, j);
            float4 h = *(const float4*)(g_hw + (long)s * 128 + lane * 4);
            ax = fmaf(v, h.x, ax); ay = fmaf(v, h.y, ay);
            az = fmaf(v, h.z, az); aw = fmaf(v, h.w, aw);
        }
    }
    float4 b = *(const float4*)(bias + lane * 4);
    ax += b.x; ay += b.y; az += b.z; aw += b.w;
    if (do_relu) {
        ax = fmaxf(0.f, ax); ay = fmaxf(0.f, ay);
        az = fmaxf(0.f, az); aw = fmaxf(0.f, aw);
    }
    *(float4*)(out + (long)warp * 640 + lane * 4) = make_float4(ax, ay, az, aw);
}

// ---------------- attention softmax (axis=1, 640) + elementwise mul ---------
__global__ void attn_kernel(const float* __restrict__ x15, int nrows) {
    int row = blockIdx.x * 8 + threadIdx.y;
    if (row >= nrows) return;
    int lane = threadIdx.x;
    float* ar = g_att + (long)row * 640;
    float z[20];
    float mx = -1e30f;
#pragma unroll
    for (int i = 0; i < 20; i++) { z[i] = ar[lane + 32 * i]; mx = fmaxf(mx, z[i]); }
#pragma unroll
    for (int o = 16; o; o >>= 1) mx = fmaxf(mx, __shfl_xor_sync(0xffffffffu, mx, o));
    float s = 0.f;
#pragma unroll
    for (int i = 0; i < 20; i++) { z[i] = expf(z[i] - mx); s += z[i]; }
#pragma unroll
    for (int o = 16; o; o >>= 1) s += __shfl_xor_sync(0xffffffffu, s, o);
    float inv = 1.0f / s;
    const float* xr = x15 + (long)row * 640;
#pragma unroll
    for (int i = 0; i < 20; i++)
        ar[lane + 32 * i] = xr[lane + 32 * i] * z[i] * inv;
}

// ---------------- fused H2+H3+log_softmax (warp per row) --------------------
// h2 = relu(bn2(h1 @ W2 + b2)) per-lane (col = lane);
// logits = h2 @ W3 + b3 via 10-value warp butterfly all-reduce; log_softmax.
__global__ __launch_bounds__(256) void h23_kernel(
    const float* __restrict__ W2, const float* __restrict__ b2,
    const float* __restrict__ g2, const float* __restrict__ bb2,
    const float* __restrict__ m2, const float* __restrict__ v2,
    const float* __restrict__ W3, const float* __restrict__ b3,
    float* __restrict__ out, int nrows)
{
    __shared__ float W2s[128 * 32];
    __shared__ float sc2[32], sh2[32];
    __shared__ float W3s[320];
    __shared__ float b3s[10];
    int t = threadIdx.x;
    for (int i = t; i < 4096; i += 256) W2s[i] = W2[i];
    for (int i = t; i < 320; i += 256)  W3s[i] = W3[i];
    if (t < 10) b3s[t] = b3[t];
    if (t < 32) {
        float s = g2[t] * rsqrtf(v2[t] + EPSBN);
        sc2[t] = s;
        sh2[t] = bb2[t] - m2[t] * s + b2[t] * s;
    }
    __syncthreads();

    int lane = t & 31;
    int r = blockIdx.x * 8 + (t >> 5);
    if (r >= nrows) return;

    // h2 column = lane
    const float* hr = g_h1 + (long)r * 128;
    float s = 0.f;
#pragma unroll
    for (int k = 0; k < 128; k++) s += __ldg(hr + k) * W2s[k * 32 + lane];
    float h2v = fmaxf(0.f, s * sc2[lane] + sh2[lane]);

    // logits: partials p[c] = h2v * W3[lane][c]; butterfly all-reduce over lanes
    float p[10];
#pragma unroll
    for (int c = 0; c < 10; c++) p[c] = h2v * W3s[lane * 10 + c];
#pragma unroll
    for (int o = 16; o; o >>= 1)
#pragma unroll
        for (int c = 0; c < 10; c++) p[c] += __shfl_xor_sync(0xffffffffu, p[c], o);

    if (lane == 0) {
#pragma unroll
        for (int c = 0; c < 10; c++) p[c] += b3s[c];
        float mx = p[0];
#pragma unroll
        for (int c = 1; c < 10; c++) mx = fmaxf(mx, p[c]);
        float se = 0.f;
#pragma unroll
        for (int c = 0; c < 10; c++) se += expf(p[c] - mx);
        float lse = mx + logf(se);
        float* o2 = out + (long)r * 10;
#pragma unroll
        for (int c = 0; c < 10; c++) o2[c] = p[c] - lse;
    }
}

// ---------------- host orchestration ----------------------------------------
extern "C" void kernel_launch(void* const* d_in, const int* in_sizes, int n_in,
                              void* d_out, int out_size)
{
    const float* x     = (const float*)d_in[0];
    const int*   esrc  = (const int*)  d_in[1];
    const int*   edst  = (const int*)  d_in[2];
    const float* evals = (const float*)d_in[3];
    const float* Wg[5] = {(const float*)d_in[4],  (const float*)d_in[6],
                          (const float*)d_in[8],  (const float*)d_in[10],
                          (const float*)d_in[12]};
    const float* bg[5] = {(const float*)d_in[5],  (const float*)d_in[7],
                          (const float*)d_in[9],  (const float*)d_in[11],
                          (const float*)d_in[13]};
    const float* Wa  = (const float*)d_in[14]; const float* ba  = (const float*)d_in[15];
    const float* H1w = (const float*)d_in[16]; const float* H1b = (const float*)d_in[17];
    const float* bn1g = (const float*)d_in[18]; const float* bn1b = (const float*)d_in[19];
    const float* bn1m = (const float*)d_in[20]; const float* bn1v = (const float*)d_in[21];
    const float* H2w = (const float*)d_in[22]; const float* H2b = (const float*)d_in[23];
    const float* bn2g = (const float*)d_in[24]; const float* bn2b = (const float*)d_in[25];
    const float* bn2m = (const float*)d_in[26]; const float* bn2v = (const float*)d_in[27];
    const float* H3w = (const float*)d_in[28]; const float* H3b = (const float*)d_in[29];
    const int E = in_sizes[1];
    (void)n_in;

    float *hw, *att, *x15f, *h1;
    __half *wthi, *wtlo;
    cudaGetSymbolAddress((void**)&hw,   g_hw);
    cudaGetSymbolAddress((void**)&att,  g_att);
    cudaGetSymbolAddress((void**)&x15f, g_x15);
    cudaGetSymbolAddress((void**)&h1,   g_h1);
    cudaGetSymbolAddress((void**)&wthi, g_wthi);
    cudaGetSymbolAddress((void**)&wtlo, g_wtlo);

    cudaFuncSetAttribute(gemm_mma_kernel,
                         cudaFuncAttributeMaxDynamicSharedMemorySize, SMEM_MMA);

    float* out = (float*)d_out;
    float* x15;
    float* logits = nullptr;
    if (out_size >= NROWS * 650)      { logits = out; x15 = out + (long)NROWS * 10; }
    else if (out_size == NROWS * 640) { x15 = out; }
    else                              { logits = out; x15 = x15f; }

    const int EB = (E + 255) / 256;
    const int RB = (NROWS * 32 + 255) / 256;
    const int GM = (NROWS + BMM - 1) / BMM;

    // ---- weight transpose + fp16 split (tiny, once per launch) ----
    const long woff[7] = {0, 65536, 147456, 245760, 360448, 491520, 901120};
    const int  wk  [7] = {512, 640, 768, 896, 1024, 640, 640};
    const int  wn  [7] = {128, 128, 128, 128, 128, 640, 128};
    const float* wsrc[7] = {Wg[0], Wg[1], Wg[2], Wg[3], Wg[4], Wa, H1w};
    for (int i = 0; i < 7; i++) {
        int total = wk[i] * wn[i];
        wsplit_kernel<<<(total + 255) / 256, 256>>>(wsrc[i],
                                                    wthi + woff[i], wtlo + woff[i],
                                                    wk[i], wn[i]);
    }

    // ---- CSR build (once; reused by all 5 layers) ----
    csr_zero_kernel<<<(NROWS + 255) / 256, 256>>>();
    csr_hist_kernel<<<EB, 256>>>(edst, E);
    csr_scan_kernel<<<1, 1024>>>();
    csr_scatter_kernel<<<EB, 256>>>(esrc, edst, evals, E);

    // ---- 5 dense-GCN layers (concat folded into two-part A) ----
    for (int L = 0; L < 5; L++) {
        int Ktot = 512 + L * 128;
        gemm_mma_kernel<<<dim3(GM, 1), 256, SMEM_MMA>>>(
            x, 512, 512, x15, 640,
            wthi + woff[L], wtlo + woff[L], Ktot,
            nullptr, nullptr, nullptr, nullptr, nullptr,
            hw, 128, NROWS, 0);
        spmm_csr_kernel<<<RB, 256>>>(bg[L], x15 + L * 128, (L == 0) ? 1 : 0);
    }

    if (logits) {
        // ---- attention: att = x15 @ Wa + ba ; a = x15 * softmax(att) ----
        gemm_mma_kernel<<<dim3(GM, 5), 256, SMEM_MMA>>>(
            x15, 640, 640, x15, 640,
            wthi + woff[5], wtlo + woff[5], 640,
            ba, nullptr, nullptr, nullptr, nullptr,
            att, 640, NROWS, 1);
        attn_kernel<<<(NROWS + 7) / 8, dim3(32, 8)>>>(x15, NROWS);
        // ---- head: h1 = relu(bn1(a @ H1w + H1b)); then fused h2+h3 ----
        gemm_mma_kernel<<<dim3(GM, 1), 256, SMEM_MMA>>>(
            att, 640, 640, att, 640,
            wthi + woff[6], wtlo + woff[6], 640,
            H1b, bn1g, bn1b, bn1m, bn1v,
            h1, 128, NROWS, 2);
        h23_kernel<<<(NROWS + 7) / 8, 256>>>(H2w, H2b, bn2g, bn2b, bn2m, bn2v,
                                             H3w, H3b, logits, NROWS);
    }
}

// round 16
// speedup vs baseline: 1.2633x; 1.1269x over previous
#include <cuda_runtime.h>
#include <cuda_fp16.h>
#include <stdint.h>

#define NROWS 100000
#define NHID  128
#define EMAX  3200000
#define EPSBN 1e-5f
#define WTOT  983040

// mma GEMM geometry (fp16x3 split, m16n8k16) — BMM=128, 2 CTAs/SM
#define BMM 128
#define BNN 128
#define KP32 12                   // uint32 (half2) stride per row: 8 data + 4 pad -> 48B
#define A_LO_OFF   6144           // bytes: 128*48
#define B_HI_OFF   12288
#define B_LO_OFF   18432
#define STAGE_B    24576
#define SMEM_MMA   49152          // 2 stages

// ---------------- scratch (no allocations allowed -> device globals) --------
__device__ float  g_hw [NROWS * NHID];
__device__ float  g_att[(size_t)NROWS * 640];
__device__ float  g_x15[(size_t)NROWS * 640];
__device__ float  g_h1 [NROWS * NHID];
// CSR build scratch
__device__ int    g_cnt [NROWS];
__device__ int    g_pos [NROWS];
__device__ int    g_rowstart[NROWS + 1];
__device__ int    g_csrc[EMAX];
__device__ float  g_cval[EMAX];
// split-fp16 transposed weights: [N, K] K-major, hi + lo parts
__device__ __half g_wthi[WTOT];
__device__ __half g_wtlo[WTOT];

// ---------------- generic-PTX helpers (sm_80-level; no tcgen05) -------------
__device__ __forceinline__ uint32_t smem_u32(const void* p) {
    uint32_t a;
    asm("{ .reg .u64 t; cvta.to.shared.u64 t, %1; cvt.u32.u64 %0, t; }"
        : "=r"(a) : "l"(p));
    return a;
}
__device__ __forceinline__ void cpasync16(uint32_t dst, const void* src) {
    asm volatile("cp.async.cg.shared.global [%0], [%1], 16;" :: "r"(dst), "l"(src));
}
#define CP_COMMIT() asm volatile("cp.async.commit_group;" ::: "memory")
#define CP_WAIT0()  asm volatile("cp.async.wait_group 0;" ::: "memory")

// fp16 mma, K=16, fp32 accumulate
__device__ __forceinline__ void mma16(float* c, const uint32_t* a,
                                      uint32_t b0, uint32_t b1) {
    asm volatile(
        "mma.sync.aligned.m16n8k16.row.col.f32.f16.f16.f32 "
        "{%0,%1,%2,%3}, {%4,%5,%6,%7}, {%8,%9}, {%0,%1,%2,%3};"
        : "+f"(c[0]), "+f"(c[1]), "+f"(c[2]), "+f"(c[3])
        : "r"(a[0]), "r"(a[1]), "r"(a[2]), "r"(a[3]), "r"(b0), "r"(b1));
}
__device__ __forceinline__ uint32_t pack_hi(float x, float y, uint32_t& lo) {
    __half hx = __float2half_rn(x);
    __half hy = __float2half_rn(y);
    __half lx = __float2half_rn(x - __half2float(hx));
    __half ly = __float2half_rn(y - __half2float(hy));
    __half2 l2 = __halves2half2(lx, ly);
    lo = *(uint32_t*)&l2;
    __half2 h2 = __halves2half2(hx, hy);
    return *(uint32_t*)&h2;
}

// ---- weight prep: W[K,N] -> hiT/loT [N,K] (fp16 hi/lo split) ---------------
__global__ void wsplit_kernel(const float* __restrict__ W,
                              __half* __restrict__ hiT, __half* __restrict__ loT,
                              int K, int N) {
    int i = blockIdx.x * 256 + threadIdx.x;
    if (i >= K * N) return;
    int k = i / N, n = i - k * N;
    float a = W[i];
    __half h = __float2half_rn(a);
    hiT[(long)n * K + k] = h;
    loT[(long)n * K + k] = __float2half_rn(a - __half2float(h));
}

// ================= fp16x3 mma.sync GEMM (BMM=128, occ 2) ====================
// C[rowTile:+128, colBase:+128] = [A0|A1] @ W  via Ahi*Bhi + Ahi*Blo + Alo*Bhi
// 4 warps as 2(M)x2(N); warp tile 64x64 (identical to R10 per-warp work).
// mode: 0 plain, 1 +bias, 2 +bias,BN-fold,ReLU
__global__ __launch_bounds__(128, 2) void gemm_mma_kernel(
    const float* __restrict__ A0, int K0, int lda0,
    const float* __restrict__ A1, int lda1,
    const __half* __restrict__ BhiT, const __half* __restrict__ BloT, int Ktot,
    const float* __restrict__ bias,
    const float* __restrict__ bng, const float* __restrict__ bnb,
    const float* __restrict__ bnm, const float* __restrict__ bnv,
    float* __restrict__ C, int ldc, int nrows, int mode)
{
    extern __shared__ char smem[];
    const int t      = threadIdx.x;
    const int lane   = t & 31;
    const int wid    = t >> 5;
    const int warp_m = wid >> 1;        // 0..1
    const int warp_n = wid & 1;         // 0..1
    const int rowTile = blockIdx.x * BMM;
    const int colBase = blockIdx.y * BNN;
    const uint32_t sbase = smem_u32(smem);

    float acc[4][8][4];
#pragma unroll
    for (int i = 0; i < 4; i++)
#pragma unroll
        for (int j = 0; j < 8; j++)
#pragma unroll
            for (int e = 0; e < 4; e++) acc[i][j][e] = 0.f;

    const int nch = Ktot >> 4;
    float4 areg[4];

    // A tile: 128 rows x 4 float4 = 512 loads / 128 threads
    auto ldA = [&](int kb) {
#pragma unroll
        for (int i = 0; i < 4; i++) {
            int id  = t + i * 128;
            int row = id >> 2, q = id & 3;
            int ar  = rowTile + row;
            float4 v = make_float4(0.f, 0.f, 0.f, 0.f);
            if (ar < nrows) {
                int kg = kb + q * 4;   // chunk never straddles K0 (both mult of 16)
                const float* ap = (kg < K0) ? A0 + (long)ar * lda0 + kg
                                            : A1 + (long)ar * lda1 + (kg - K0);
                v = *(const float4*)ap;
            }
            areg[i] = v;
        }
    };
    // split + STS A regs into stage s (half2 hi/lo)
    auto stA = [&](int s) {
        char* base = smem + s * STAGE_B;
#pragma unroll
        for (int i = 0; i < 4; i++) {
            int id  = t + i * 128;
            int row = id >> 2, q = id & 3;
            float4 v = areg[i];
            uint32_t lo0, lo1;
            uint32_t hi0 = pack_hi(v.x, v.y, lo0);
            uint32_t hi1 = pack_hi(v.z, v.w, lo1);
            int off = row * 48 + q * 8;            // bytes
            *(uint2*)(base + off)            = make_uint2(hi0, hi1);
            *(uint2*)(base + A_LO_OFF + off) = make_uint2(lo0, lo1);
        }
    };
    // B cp.async into stage s: 128 n-rows x (hi,lo) x 2 16B = 512 copies / 128 thr
    auto cpB = [&](int s, int kb) {
        uint32_t dst0 = sbase + s * STAGE_B;
#pragma unroll
        for (int i = 0; i < 4; i++) {
            int id   = t + i * 128;
            int n    = id >> 2;
            int rem  = id & 3;
            int part = rem >> 1, q = rem & 1;
            const __half* src = (part ? BloT : BhiT)
                                + (long)(colBase + n) * Ktot + kb + q * 8;
            uint32_t dst = dst0 + (part ? B_LO_OFF : B_HI_OFF) + n * 48 + q * 16;
            cpasync16(dst, src);
        }
    };
    auto compute = [&](int s) {
        const uint32_t* sAh = (const uint32_t*)(smem + s * STAGE_B);
        const uint32_t* sAl = (const uint32_t*)(smem + s * STAGE_B + A_LO_OFF);
        const uint32_t* sBh = (const uint32_t*)(smem + s * STAGE_B + B_HI_OFF);
        const uint32_t* sBl = (const uint32_t*)(smem + s * STAGE_B + B_LO_OFF);
        const int mrow = warp_m * 64 + (lane >> 2);
        const int nrow = warp_n * 64 + (lane >> 2);
        const int kq   = lane & 3;
        uint32_t ah[4][4], al[4][4];
#pragma unroll
        for (int mf = 0; mf < 4; mf++) {
            int m0 = mrow + mf * 16;
            ah[mf][0] = sAh[m0 * KP32 + kq];      ah[mf][1] = sAh[(m0 + 8) * KP32 + kq];
            ah[mf][2] = sAh[m0 * KP32 + kq + 4];  ah[mf][3] = sAh[(m0 + 8) * KP32 + kq + 4];
            al[mf][0] = sAl[m0 * KP32 + kq];      al[mf][1] = sAl[(m0 + 8) * KP32 + kq];
            al[mf][2] = sAl[m0 * KP32 + kq + 4];  al[mf][3] = sAl[(m0 + 8) * KP32 + kq + 4];
        }
#pragma unroll
        for (int nf = 0; nf < 8; nf++) {
            int n0 = nrow + nf * 8;
            uint32_t bh0 = sBh[n0 * KP32 + kq], bh1 = sBh[n0 * KP32 + kq + 4];
            uint32_t bl0 = sBl[n0 * KP32 + kq], bl1 = sBl[n0 * KP32 + kq + 4];
#pragma unroll
            for (int mf = 0; mf < 4; mf++) {
                mma16(acc[mf][nf], ah[mf], bh0, bh1);
                mma16(acc[mf][nf], ah[mf], bl0, bl1);
                mma16(acc[mf][nf], al[mf], bh0, bh1);
            }
        }
    };

    // ---- prologue ----
    ldA(0);
    cpB(0, 0);
    CP_COMMIT();
    stA(0);
    CP_WAIT0();
    __syncthreads();

    // ---- mainloop (R10-proven 2-stage schedule) ----
    for (int ch = 0; ch < nch; ch++) {
        const int s = ch & 1;
        const bool more = (ch + 1 < nch);
        if (more) { ldA((ch + 1) << 4); cpB(s ^ 1, (ch + 1) << 4); CP_COMMIT(); }
        compute(s);
        if (more) { stA(s ^ 1); CP_WAIT0(); }
        __syncthreads();
    }

    // ---- epilogue ----
#pragma unroll
    for (int mf = 0; mf < 4; mf++) {
        int r0 = rowTile + warp_m * 64 + mf * 16 + (lane >> 2);
#pragma unroll
        for (int nf = 0; nf < 8; nf++) {
            int cc = colBase + warp_n * 64 + nf * 8 + (lane & 3) * 2;
            float v0 = acc[mf][nf][0], v1 = acc[mf][nf][1];
            float v2 = acc[mf][nf][2], v3 = acc[mf][nf][3];
            if (mode == 1) {
                float b0 = bias[cc], b1 = bias[cc + 1];
                v0 += b0; v1 += b1; v2 += b0; v3 += b1;
            } else if (mode == 2) {
                float s0 = bng[cc]     * rsqrtf(bnv[cc]     + EPSBN);
                float s1 = bng[cc + 1] * rsqrtf(bnv[cc + 1] + EPSBN);
                float h0 = bnb[cc]     - bnm[cc]     * s0 + bias[cc]     * s0;
                float h1 = bnb[cc + 1] - bnm[cc + 1] * s1 + bias[cc + 1] * s1;
                v0 = fmaxf(0.f, v0 * s0 + h0); v1 = fmaxf(0.f, v1 * s1 + h1);
                v2 = fmaxf(0.f, v2 * s0 + h0); v3 = fmaxf(0.f, v3 * s1 + h1);
            }
            if (r0 < nrows)
                *(float2*)(C + (long)r0 * ldc + cc) = make_float2(v0, v1);
            if (r0 + 8 < nrows)
                *(float2*)(C + (long)(r0 + 8) * ldc + cc) = make_float2(v2, v3);
        }
    }
}

// ================= CSR build (once per launch; deterministic work) ==========
__global__ void csr_zero_kernel() {
    int i = blockIdx.x * blockDim.x + threadIdx.x;
    if (i < NROWS) { g_cnt[i] = 0; g_pos[i] = 0; }
}
__global__ void csr_hist_kernel(const int* __restrict__ dst, int E) {
    int e = blockIdx.x * blockDim.x + threadIdx.x;
    if (e < E) atomicAdd(&g_cnt[dst[e]], 1);
}
__global__ __launch_bounds__(1024) void csr_scan_kernel() {
    __shared__ int wsum[32];
    __shared__ int carry_s;
    const int t = threadIdx.x, lane = t & 31, w = t >> 5;
    if (t == 0) carry_s = 0;
    __syncthreads();
    for (int base = 0; base < NROWS; base += 1024) {
        int xv = (base + t < NROWS) ? g_cnt[base + t] : 0;
        int val = xv;
#pragma unroll
        for (int o = 1; o < 32; o <<= 1) {
            int y = __shfl_up_sync(0xffffffffu, val, o);
            if (lane >= o) val += y;
        }
        if (lane == 31) wsum[w] = val;
        __syncthreads();
        if (w == 0) {
            int s = wsum[lane];
#pragma unroll
            for (int o = 1; o < 32; o <<= 1) {
                int y = __shfl_up_sync(0xffffffffu, s, o);
                if (lane >= o) s += y;
            }
            wsum[lane] = s;
        }
        __syncthreads();
        int incl = val + (w ? wsum[w - 1] : 0) + carry_s;
        if (base + t < NROWS) g_rowstart[base + t] = incl - xv;
        __syncthreads();
        if (t == 1023) carry_s = incl;
        __syncthreads();
    }
    if (threadIdx.x == 0) g_rowstart[NROWS] = carry_s;
}
__global__ void csr_scatter_kernel(const int* __restrict__ src,
                                   const int* __restrict__ dst,
                                   const float* __restrict__ vals, int E) {
    int e = blockIdx.x * blockDim.x + threadIdx.x;
    if (e < E) {
        int d = dst[e];
        int p = g_rowstart[d] + atomicAdd(&g_pos[d], 1);
        g_csrc[p] = src[e];
        g_cval[p] = vals[e];
    }
}

// ---- SpMM segment-sum: warp per dst row, no atomics ------------------------
__global__ __launch_bounds__(256) void spmm_csr_kernel(
    const float* __restrict__ bias,
    float* __restrict__ out,   // x15 + col-block base, ld 640
    int do_relu)
{
    const int warp = (blockIdx.x * blockDim.x + threadIdx.x) >> 5;
    if (warp >= NROWS) return;
    const int lane = threadIdx.x & 31;
    const int s0 = g_rowstart[warp];
    const int s1 = g_rowstart[warp + 1];

    float ax = 0.f, ay = 0.f, az = 0.f, aw = 0.f;
    for (int base = s0; base < s1; base += 32) {
        int n = min(32, s1 - base);
        int   ss = 0; float vv = 0.f;
        if (lane < n) { ss = g_csrc[base + lane]; vv = g_cval[base + lane]; }
        for (int j = 0; j < n; j++) {
            int   s = __shfl_sync(0xffffffffu, ss, j);
            float v = __shfl_sync(0xffffffffu, vv, j);
            float4 h = *(const float4*)(g_hw + (long)s * 128 + lane * 4);
            ax = fmaf(v, h.x, ax); ay = fmaf(v, h.y, ay);
            az = fmaf(v, h.z, az); aw = fmaf(v, h.w, aw);
        }
    }
    float4 b = *(const float4*)(bias + lane * 4);
    ax += b.x; ay += b.y; az += b.z; aw += b.w;
    if (do_relu) {
        ax = fmaxf(0.f, ax); ay = fmaxf(0.f, ay);
        az = fmaxf(0.f, az); aw = fmaxf(0.f, aw);
    }
    *(float4*)(out + (long)warp * 640 + lane * 4) = make_float4(ax, ay, az, aw);
}

// ---------------- attention softmax (axis=1, 640) + elementwise mul ---------
__global__ void attn_kernel(const float* __restrict__ x15, int nrows) {
    int row = blockIdx.x * 8 + threadIdx.y;
    if (row >= nrows) return;
    int lane = threadIdx.x;
    float* ar = g_att + (long)row * 640;
    float z[20];
    float mx = -1e30f;
#pragma unroll
    for (int i = 0; i < 20; i++) { z[i] = ar[lane + 32 * i]; mx = fmaxf(mx, z[i]); }
#pragma unroll
    for (int o = 16; o; o >>= 1) mx = fmaxf(mx, __shfl_xor_sync(0xffffffffu, mx, o));
    float s = 0.f;
#pragma unroll
    for (int i = 0; i < 20; i++) { z[i] = expf(z[i] - mx); s += z[i]; }
#pragma unroll
    for (int o = 16; o; o >>= 1) s += __shfl_xor_sync(0xffffffffu, s, o);
    float inv = 1.0f / s;
    const float* xr = x15 + (long)row * 640;
#pragma unroll
    for (int i = 0; i < 20; i++)
        ar[lane + 32 * i] = xr[lane + 32 * i] * z[i] * inv;
}

// ---------------- fused H2+H3+log_softmax (warp per row) --------------------
__global__ __launch_bounds__(256) void h23_kernel(
    const float* __restrict__ W2, const float* __restrict__ b2,
    const float* __restrict__ g2, const float* __restrict__ bb2,
    const float* __restrict__ m2, const float* __restrict__ v2,
    const float* __restrict__ W3, const float* __restrict__ b3,
    float* __restrict__ out, int nrows)
{
    __shared__ float W2s[128 * 32];
    __shared__ float sc2[32], sh2[32];
    __shared__ float W3s[320];
    __shared__ float b3s[10];
    int t = threadIdx.x;
    for (int i = t; i < 4096; i += 256) W2s[i] = W2[i];
    for (int i = t; i < 320; i += 256)  W3s[i] = W3[i];
    if (t < 10) b3s[t] = b3[t];
    if (t < 32) {
        float s = g2[t] * rsqrtf(v2[t] + EPSBN);
        sc2[t] = s;
        sh2[t] = bb2[t] - m2[t] * s + b2[t] * s;
    }
    __syncthreads();

    int lane = t & 31;
    int r = blockIdx.x * 8 + (t >> 5);
    if (r >= nrows) return;

    const float* hr = g_h1 + (long)r * 128;
    float s = 0.f;
#pragma unroll
    for (int k = 0; k < 128; k++) s += __ldg(hr + k) * W2s[k * 32 + lane];
    float h2v = fmaxf(0.f, s * sc2[lane] + sh2[lane]);

    float p[10];
#pragma unroll
    for (int c = 0; c < 10; c++) p[c] = h2v * W3s[lane * 10 + c];
#pragma unroll
    for (int o = 16; o; o >>= 1)
#pragma unroll
        for (int c = 0; c < 10; c++) p[c] += __shfl_xor_sync(0xffffffffu, p[c], o);

    if (lane == 0) {
#pragma unroll
        for (int c = 0; c < 10; c++) p[c] += b3s[c];
        float mx = p[0];
#pragma unroll
        for (int c = 1; c < 10; c++) mx = fmaxf(mx, p[c]);
        float se = 0.f;
#pragma unroll
        for (int c = 0; c < 10; c++) se += expf(p[c] - mx);
        float lse = mx + logf(se);
        float* o2 = out + (long)r * 10;
#pragma unroll
        for (int c = 0; c < 10; c++) o2[c] = p[c] - lse;
    }
}

// ---------------- host orchestration ----------------------------------------
extern "C" void kernel_launch(void* const* d_in, const int* in_sizes, int n_in,
                              void* d_out, int out_size)
{
    const float* x     = (const float*)d_in[0];
    const int*   esrc  = (const int*)  d_in[1];
    const int*   edst  = (const int*)  d_in[2];
    const float* evals = (const float*)d_in[3];
    const float* Wg[5] = {(const float*)d_in[4],  (const float*)d_in[6],
                          (const float*)d_in[8],  (const float*)d_in[10],
                          (const float*)d_in[12]};
    const float* bg[5] = {(const float*)d_in[5],  (const float*)d_in[7],
                          (const float*)d_in[9],  (const float*)d_in[11],
                          (const float*)d_in[13]};
    const float* Wa  = (const float*)d_in[14]; const float* ba  = (const float*)d_in[15];
    const float* H1w = (const float*)d_in[16]; const float* H1b = (const float*)d_in[17];
    const float* bn1g = (const float*)d_in[18]; const float* bn1b = (const float*)d_in[19];
    const float* bn1m = (const float*)d_in[20]; const float* bn1v = (const float*)d_in[21];
    const float* H2w = (const float*)d_in[22]; const float* H2b = (const float*)d_in[23];
    const float* bn2g = (const float*)d_in[24]; const float* bn2b = (const float*)d_in[25];
    const float* bn2m = (const float*)d_in[26]; const float* bn2v = (const float*)d_in[27];
    const float* H3w = (const float*)d_in[28]; const float* H3b = (const float*)d_in[29];
    const int E = in_sizes[1];
    (void)n_in;

    float *hw, *att, *x15f, *h1;
    __half *wthi, *wtlo;
    cudaGetSymbolAddress((void**)&hw,   g_hw);
    cudaGetSymbolAddress((void**)&att,  g_att);
    cudaGetSymbolAddress((void**)&x15f, g_x15);
    cudaGetSymbolAddress((void**)&h1,   g_h1);
    cudaGetSymbolAddress((void**)&wthi, g_wthi);
    cudaGetSymbolAddress((void**)&wtlo, g_wtlo);

    cudaFuncSetAttribute(gemm_mma_kernel,
                         cudaFuncAttributeMaxDynamicSharedMemorySize, SMEM_MMA);

    float* out = (float*)d_out;
    float* x15;
    float* logits = nullptr;
    if (out_size >= NROWS * 650)      { logits = out; x15 = out + (long)NROWS * 10; }
    else if (out_size == NROWS * 640) { x15 = out; }
    else                              { logits = out; x15 = x15f; }

    const int EB = (E + 255) / 256;
    const int RB = (NROWS * 32 + 255) / 256;
    const int GM = (NROWS + BMM - 1) / BMM;   // 782 row-tiles

    // ---- weight transpose + fp16 split (tiny, once per launch) ----
    const long woff[7] = {0, 65536, 147456, 245760, 360448, 491520, 901120};
    const int  wk  [7] = {512, 640, 768, 896, 1024, 640, 640};
    const int  wn  [7] = {128, 128, 128, 128, 128, 640, 128};
    const float* wsrc[7] = {Wg[0], Wg[1], Wg[2], Wg[3], Wg[4], Wa, H1w};
    for (int i = 0; i < 7; i++) {
        int total = wk[i] * wn[i];
        wsplit_kernel<<<(total + 255) / 256, 256>>>(wsrc[i],
                                                    wthi + woff[i], wtlo + woff[i],
                                                    wk[i], wn[i]);
    }

    // ---- CSR build (once; reused by all 5 layers) ----
    csr_zero_kernel<<<(NROWS + 255) / 256, 256>>>();
    csr_hist_kernel<<<EB, 256>>>(edst, E);
    csr_scan_kernel<<<1, 1024>>>();
    csr_scatter_kernel<<<EB, 256>>>(esrc, edst, evals, E);

    // ---- 5 dense-GCN layers (concat folded into two-part A) ----
    for (int L = 0; L < 5; L++) {
        int Ktot = 512 + L * 128;
        gemm_mma_kernel<<<dim3(GM, 1), 128, SMEM_MMA>>>(
            x, 512, 512, x15, 640,
            wthi + woff[L], wtlo + woff[L], Ktot,
            nullptr, nullptr, nullptr, nullptr, nullptr,
            hw, 128, NROWS, 0);
        spmm_csr_kernel<<<RB, 256>>>(bg[L], x15 + L * 128, (L == 0) ? 1 : 0);
    }

    if (logits) {
        // ---- attention: att = x15 @ Wa + ba ; a = x15 * softmax(att) ----
        gemm_mma_kernel<<<dim3(GM, 5), 128, SMEM_MMA>>>(
            x15, 640, 640, x15, 640,
            wthi + woff[5], wtlo + woff[5], 640,
            ba, nullptr, nullptr, nullptr, nullptr,
            att, 640, NROWS, 1);
        attn_kernel<<<(NROWS + 7) / 8, dim3(32, 8)>>>(x15, NROWS);
        // ---- head: h1 = relu(bn1(a @ H1w + H1b)); then fused h2+h3 ----
        gemm_mma_kernel<<<dim3(GM, 1), 128, SMEM_MMA>>>(
            att, 640, 640, att, 640,
            wthi + woff[6], wtlo + woff[6], 640,
            H1b, bn1g, bn1b, bn1m, bn1v,
            h1, 128, NROWS, 2);
        h23_kernel<<<(NROWS + 7) / 8, 256>>>(H2w, H2b, bn2g, bn2b, bn2m, bn2v,
                                             H3w, H3b, logits, NROWS);
    }
}